// round 11
// baseline (speedup 1.0000x reference)
#include <cuda_runtime.h>
#include <math.h>

#define BB   256

// out layout: value [B,32,32,32] | weight [B,32,32] | wp [B,32,32]
#define WOFF      (8388608ull)
#define WPOFF     (8650752ull)

typedef unsigned long long ull;

__device__ float g_M [128 * 128];
__device__ float g_Mp[128 * 128];
__device__ float g_U [BB * 32 * 64];
__device__ float g_V [BB * 32 * 64];
__device__ unsigned g_W2h[64 * 32];
__device__ unsigned g_W2l[64 * 32];

// ---- packed f32x2 helpers ----
__device__ __forceinline__ ull pk2(float v) {
    ull r; asm("mov.b64 %0, {%1, %1};" : "=l"(r) : "f"(v)); return r;
}
__device__ __forceinline__ ull ffma2(ull a, ull b, ull c) {
    ull d; asm("fma.rn.f32x2 %0, %1, %2, %3;" : "=l"(d) : "l"(a), "l"(b), "l"(c)); return d;
}
__device__ __forceinline__ float2 upk2(ull v) {
    float2 f; asm("mov.b64 {%0, %1}, %2;" : "=f"(f.x), "=f"(f.y) : "l"(v)); return f;
}

// ---- tf32 helpers ----
__device__ __forceinline__ unsigned tf32_of(float x) {
    unsigned r; asm("cvt.rna.tf32.f32 %0, %1;" : "=r"(r) : "f"(x)); return r;
}
__device__ __forceinline__ void mma_tf32(float d[4], const unsigned a[4],
                                         unsigned b0, unsigned b1) {
    asm("mma.sync.aligned.m16n8k8.row.col.f32.tf32.tf32.f32 "
        "{%0,%1,%2,%3}, {%4,%5,%6,%7}, {%8,%9}, {%0,%1,%2,%3};"
        : "+f"(d[0]), "+f"(d[1]), "+f"(d[2]), "+f"(d[3])
        : "r"(a[0]), "r"(a[1]), "r"(a[2]), "r"(a[3]), "r"(b0), "r"(b1));
}

__device__ __forceinline__ float warp_max(float v) {
    #pragma unroll
    for (int o = 16; o; o >>= 1) v = fmaxf(v, __shfl_xor_sync(0xffffffffu, v, o));
    return v;
}
__device__ __forceinline__ float warp_sum(float v) {
    #pragma unroll
    for (int o = 16; o; o >>= 1) v += __shfl_xor_sync(0xffffffffu, v, o);
    return v;
}

// ---------------------------------------------------------------------------
// Kernel 0 (round-9 measured 9.0us): M/Mp GEMMs + W2 hi/lo split.
// ---------------------------------------------------------------------------
__global__ void k0_all(const float* __restrict__ Wq, const float* __restrict__ Wk,
                       const float* __restrict__ Wqp, const float* __restrict__ Wkp,
                       const float* __restrict__ Wf2) {
    const int bx = blockIdx.x;
    const int t  = threadIdx.x;
    if (bx >= 256) {
        int idx = (bx - 256) * 256 + t;
        float v = Wf2[idx];
        unsigned h = tf32_of(v);
        g_W2h[idx] = h;
        g_W2l[idx] = tf32_of(v - __uint_as_float(h));
        return;
    }
    __shared__ float sA[8 * 128];
    __shared__ float sB[16 * 129];
    __shared__ float sR[128 * 2];
    const int mat = bx >> 7;
    const int e0  = ((bx >> 3) & 15) * 8;
    const int c0  = (bx & 7) * 16;
    const float* A  = mat ? Wqp : Wq;
    const float* Bm = mat ? Wkp : Wk;
    float* out      = mat ? g_Mp : g_M;
    for (int i = t; i < 1024; i += 256) sA[i] = A[e0 * 128 + i];
    for (int i = t; i < 2048; i += 256) {
        int r = i >> 7, d = i & 127;
        sB[r * 129 + d] = Bm[(c0 + r) * 128 + d];
    }
    __syncthreads();
    const int kh = t >> 7, r = (t >> 4) & 7, c = t & 15;
    float acc = 0.f;
    const int d0 = kh * 64;
    #pragma unroll 8
    for (int d = 0; d < 64; ++d)
        acc = fmaf(sA[r * 128 + d0 + d], sB[c * 129 + d0 + d], acc);
    sR[(r * 16 + c) * 2 + kh] = acc;
    __syncthreads();
    if (t < 128) {
        int rr = t >> 4, cc = t & 15;
        out[(e0 + rr) * 128 + c0 + cc] = sR[t * 2] + sR[t * 2 + 1];
    }
}

// ---------------------------------------------------------------------------
// k1 staged fp32 GEMM cores (round-7 proven, untouched).
// ---------------------------------------------------------------------------
__device__ __forceinline__ void mm_chunk128(const float* __restrict__ X, int xstr, int e0,
                                            const float* __restrict__ Ws,
                                            ull acc[4][2], int r0, int l) {
    #pragma unroll 4
    for (int e = 0; e < 32; ++e) {
        ulonglong2 wv = *reinterpret_cast<const ulonglong2*>(&Ws[e * 128 + 4 * l]);
        #pragma unroll
        for (int r = 0; r < 4; ++r) {
            ull xx = pk2(X[(r0 + r) * xstr + e0 + e]);
            acc[r][0] = ffma2(xx, wv.x, acc[r][0]);
            acc[r][1] = ffma2(xx, wv.y, acc[r][1]);
        }
    }
}

__device__ __forceinline__ void mm_chunk64(const float* __restrict__ X, int e0,
                                           const float* __restrict__ Ws,
                                           ull acc[4], int r0, int l) {
    #pragma unroll 4
    for (int e = 0; e < 64; ++e) {
        ull wv = *reinterpret_cast<const ull*>(&Ws[e * 64 + 2 * l]);
        #pragma unroll
        for (int r = 0; r < 4; ++r)
            acc[r] = ffma2(pk2(X[(r0 + r) * 128 + e0 + e]), wv, acc[r]);
    }
}

__device__ __forceinline__ void store128(float* __restrict__ Y, ull acc[4][2],
                                         int r0, int l, bool do_tanh) {
    #pragma unroll
    for (int r = 0; r < 4; ++r) {
        float2 p0 = upk2(acc[r][0]);
        float2 p1 = upk2(acc[r][1]);
        float4 v = make_float4(p0.x, p0.y, p1.x, p1.y);
        if (do_tanh) { v.x = tanhf(v.x); v.y = tanhf(v.y); v.z = tanhf(v.z); v.w = tanhf(v.w); }
        *reinterpret_cast<float4*>(&Y[(r0 + r) * 128 + 4 * l]) = v;
    }
}

// ---------------------------------------------------------------------------
// Kernel 1 (round-7 exact): one block per batch. smem 90,496 B -> 2 blocks/SM.
// ---------------------------------------------------------------------------
#define SM1_BYTES 90496
#define SOFTMAX_SCALE 0.08838834764831843f   // 1/sqrt(128)

#define STAGE(SRC) do {                                                    \
    __syncthreads();                                                       \
    { const float4* s4 = reinterpret_cast<const float4*>(SRC);            \
      float4* d4 = reinterpret_cast<float4*>(s_Wst);                      \
      for (int i = t; i < 1024; i += 256) d4[i] = s4[i]; }                \
    __syncthreads();                                                       \
} while (0)

extern "C" __global__ void __launch_bounds__(256, 2)
k1_batch(const float* __restrict__ states, const float* __restrict__ policies,
         const float* __restrict__ actions, const float* __restrict__ states_people,
         const float* __restrict__ actions_people,
         const float* __restrict__ Wv, const float* __restrict__ Wvp,
         const float* __restrict__ Wf1, float* __restrict__ out) {
    extern __shared__ __align__(16) float sm[];
    float* s_oa  = sm;                 // 32 x 129
    float* s_oap = s_oa  + 4128;       // 32 x 129
    float* s_t   = s_oap + 4128;       // 32 x 128
    float* s_w   = s_t   + 4096;       // 32 x 32
    float* s_wp  = s_w   + 1024;       // 32 x 33
    float* s_A1  = s_wp  + 1056;       // 32 x 64  (early: sc 32x33)
    float* s_C1  = s_A1  + 2048;       // 32 x 64  (early: sp 32x33)
    float* s_Wst = s_C1  + 2048;       // 4096 floats: weight chunk buffer
    float* s_sc  = s_A1;
    float* s_sp  = s_C1;

    const int b = blockIdx.x;
    const int t = threadIdx.x;
    const int w = t >> 5, l = t & 31, r0 = 4 * w;

    const float* ac = actions  + (size_t)b * 1024;
    const float* po = policies + (size_t)b * 1024;

    float d_r[4];
    #pragma unroll
    for (int r = 0; r < 4; ++r)
        d_r[r] = po[(r0 + r) * 32 + l] - ac[(r0 + r) * 32 + l];

    {
        const float* st  = states         + (size_t)b * 32 * 96;
        const float* stp = states_people  + (size_t)b * 32 * 96;
        const float* acp = actions_people + (size_t)b * 1024;
        for (int idx = t; idx < 4096; idx += 256) {
            int i = idx >> 7, c = idx & 127;
            s_oa [i * 129 + c] = (c < 96) ? st [i * 96 + c] : ac [i * 32 + c - 96];
            s_oap[i * 129 + c] = (c < 96) ? stp[i * 96 + c] : acp[i * 32 + c - 96];
        }
    }

    // --- t = oa @ M (staged); scores -> sc ---
    {
        ull a1[4][2] = {{0,0},{0,0},{0,0},{0,0}};
        #pragma unroll 1
        for (int ck = 0; ck < 4; ++ck) {
            STAGE(g_M + ck * 4096);
            mm_chunk128(s_oa, 129, ck * 32, s_Wst, a1, r0, l);
        }
        store128(s_t, a1, r0, l, false);
        float a0 = 0, s1 = 0, s2 = 0, s3 = 0;
        #pragma unroll 4
        for (int f = 0; f < 128; ++f) {
            float oj = s_oa[l * 129 + f];
            a0 = fmaf(s_t[(r0 + 0) * 128 + f], oj, a0);
            s1 = fmaf(s_t[(r0 + 1) * 128 + f], oj, s1);
            s2 = fmaf(s_t[(r0 + 2) * 128 + f], oj, s2);
            s3 = fmaf(s_t[(r0 + 3) * 128 + f], oj, s3);
        }
        s_sc[(r0 + 0) * 33 + l] = a0;  s_sc[(r0 + 1) * 33 + l] = s1;
        s_sc[(r0 + 2) * 33 + l] = s2;  s_sc[(r0 + 3) * 33 + l] = s3;
    }

    // --- tp = oa @ Mp (staged); scores_p -> sp ---
    {
        ull a2[4][2] = {{0,0},{0,0},{0,0},{0,0}};
        #pragma unroll 1
        for (int ck = 0; ck < 4; ++ck) {
            STAGE(g_Mp + ck * 4096);
            mm_chunk128(s_oa, 129, ck * 32, s_Wst, a2, r0, l);
        }
        store128(s_t, a2, r0, l, false);
        float c0 = 0, c1 = 0, c2 = 0, c3 = 0;
        #pragma unroll 4
        for (int f = 0; f < 128; ++f) {
            float pj = s_oap[l * 129 + f];
            c0 = fmaf(s_t[(r0 + 0) * 128 + f], pj, c0);
            c1 = fmaf(s_t[(r0 + 1) * 128 + f], pj, c1);
            c2 = fmaf(s_t[(r0 + 2) * 128 + f], pj, c2);
            c3 = fmaf(s_t[(r0 + 3) * 128 + f], pj, c3);
        }
        s_sp[(r0 + 0) * 33 + l] = c0;  s_sp[(r0 + 1) * 33 + l] = c1;
        s_sp[(r0 + 2) * 33 + l] = c2;  s_sp[(r0 + 3) * 33 + l] = c3;
    }
    __syncthreads();

    // --- column softmaxes ---
    {
        #pragma unroll
        for (int k = 0; k < 4; ++k) {
            int a = w + 8 * k;
            float v  = s_sc[l * 33 + a] * SOFTMAX_SCALE;
            float m  = warp_max(v);
            float e  = expf(v - m);
            float s  = warp_sum(e);
            float wg = e / s;
            s_w[a * 32 + l] = wg;
            out[WOFF + ((size_t)b * 32 + a) * 32 + l] = wg;
            float v2 = s_sp[l * 33 + a] * SOFTMAX_SCALE;
            float m2 = warp_max(v2);
            float e2 = expf(v2 - m2);
            float s2 = warp_sum(e2);
            s_wp[l * 33 + a] = e2 / s2;
        }
    }
    __syncthreads();

    // === va -> A1 ; vp -> V(gmem) ; avp -> C1 ===
    ull a1regs[4];
    {
        ull av[4][2] = {{0,0},{0,0},{0,0},{0,0}};
        #pragma unroll 1
        for (int ck = 0; ck < 4; ++ck) {
            STAGE(Wv + ck * 4096);
            mm_chunk128(s_oa, 129, ck * 32, s_Wst, av, r0, l);
        }
        ull va_pre[4][2];
        #pragma unroll
        for (int r = 0; r < 4; ++r) { va_pre[r][0] = av[r][0]; va_pre[r][1] = av[r][1]; }
        store128(s_t, av, r0, l, true);

        {
            ull acc[4] = {0, 0, 0, 0};
            #pragma unroll 1
            for (int ck = 0; ck < 2; ++ck) {
                STAGE(Wf1 + ck * 4096);
                mm_chunk64(s_t, ck * 64, s_Wst, acc, r0, l);
            }
            #pragma unroll
            for (int r = 0; r < 4; ++r) {
                a1regs[r] = acc[r];
                *reinterpret_cast<float2*>(&s_A1[(r0 + r) * 64 + 2 * l]) = upk2(acc[r]);
            }
        }

        {
            STAGE(Wv + 96 * 128);
            #pragma unroll 4
            for (int e = 0; e < 32; ++e) {
                ulonglong2 wv = *reinterpret_cast<const ulonglong2*>(&s_Wst[e * 128 + 4 * l]);
                #pragma unroll
                for (int r = 0; r < 4; ++r) {
                    ull xx = pk2(__shfl_sync(0xffffffffu, d_r[r], e));
                    va_pre[r][0] = ffma2(xx, wv.x, va_pre[r][0]);
                    va_pre[r][1] = ffma2(xx, wv.y, va_pre[r][1]);
                }
            }
            store128(s_t, va_pre, r0, l, true);
        }

        {
            ull acc[4] = {0, 0, 0, 0};
            #pragma unroll 1
            for (int ck = 0; ck < 2; ++ck) {
                STAGE(Wf1 + ck * 4096);
                mm_chunk64(s_t, ck * 64, s_Wst, acc, r0, l);
            }
            float* gV = g_V + (size_t)b * 2048;
            #pragma unroll
            for (int r = 0; r < 4; ++r) {
                float2 p = upk2(acc[r]);
                float2 a = upk2(a1regs[r]);
                *reinterpret_cast<float2*>(&gV[(r0 + r) * 64 + 2 * l]) =
                    make_float2((p.x - a.x) * 0.03125f, (p.y - a.y) * 0.03125f);
            }
        }

        {
            ull ap[4][2] = {{0,0},{0,0},{0,0},{0,0}};
            #pragma unroll 1
            for (int ck = 0; ck < 4; ++ck) {
                STAGE(Wvp + ck * 4096);
                mm_chunk128(s_oap, 129, ck * 32, s_Wst, ap, r0, l);
            }
            store128(s_t, ap, r0, l, true);
            ull acc[4] = {0, 0, 0, 0};
            #pragma unroll 1
            for (int ck = 0; ck < 2; ++ck) {
                STAGE(Wf1 + 8192 + ck * 4096);
                mm_chunk64(s_t, ck * 64, s_Wst, acc, r0, l);
            }
            #pragma unroll
            for (int r = 0; r < 4; ++r)
                *reinterpret_cast<float2*>(&s_C1[(r0 + r) * 64 + 2 * l]) = upk2(acc[r]);
        }
    }
    __syncthreads();

    for (int idx = t; idx < 1024; idx += 256)
        out[WPOFF + (size_t)b * 1024 + idx] = s_wp[(idx >> 5) * 33 + (idx & 31)];

    {
        const ull* A1u = reinterpret_cast<const ull*>(s_A1);
        const ull* C1u = reinterpret_cast<const ull*>(s_C1);
        ull uacc[4] = {0, 0, 0, 0};
        #pragma unroll 4
        for (int j = 0; j < 32; ++j) {
            ull wv = A1u[j * 32 + l];
            #pragma unroll
            for (int r = 0; r < 4; ++r)
                uacc[r] = ffma2(pk2(s_w[(r0 + r) * 32 + j]), wv, uacc[r]);
        }
        #pragma unroll 4
        for (int p = 0; p < 32; ++p) {
            ull wv = C1u[p * 32 + l];
            #pragma unroll
            for (int r = 0; r < 4; ++r)
                uacc[r] = ffma2(pk2(s_wp[(r0 + r) * 33 + p]), wv, uacc[r]);
        }
        float* gU = g_U + (size_t)b * 2048;
        #pragma unroll
        for (int r = 0; r < 4; ++r) {
            float2 p = upk2(uacc[r]);
            *reinterpret_cast<float2*>(&gU[(r0 + r) * 64 + 2 * l]) =
                make_float2(p.x * 0.03125f, p.y * 0.03125f);
        }
    }
}

// ---------------------------------------------------------------------------
// Kernel 2 (MERGED): one block per batch; warp w -> agents 4w..4w+3.
// Loads V/U/weight/W2 once per batch (was 4x), single wave (256 <= 444).
// ---------------------------------------------------------------------------
extern "C" __global__ void __launch_bounds__(256, 3)
k2_value(float* __restrict__ out) {
    __shared__ float    sV [32 * 68];
    __shared__ float    sU [32 * 64];
    __shared__ float    swt[32 * 32];
    __shared__ unsigned sW2h[64 * 36];
    __shared__ unsigned sW2l[64 * 36];

    const int t = threadIdx.x;
    const int b = blockIdx.x;

    for (int idx = t; idx < 2048; idx += 256) {
        int i = idx >> 6, f = idx & 63;
        sV[i * 68 + f] = g_V[(size_t)b * 2048 + idx];
    }
    for (int idx = t; idx < 2048; idx += 256)
        sU[idx] = g_U[(size_t)b * 2048 + idx];
    for (int idx = t; idx < 1024; idx += 256)
        swt[idx] = out[WOFF + (size_t)b * 1024 + idx];
    for (int idx = t; idx < 2048; idx += 256) {
        int f = idx >> 5, n = idx & 31;
        sW2h[f * 36 + n] = g_W2h[idx];
        sW2l[f * 36 + n] = g_W2l[idx];
    }
    __syncthreads();

    const int w = t >> 5, l = t & 31;
    const int lq = l >> 2, lr = l & 3;

    #pragma unroll 1
    for (int r = 0; r < 4; ++r) {
        const int a = 4 * w + r;
        const float* Urow = &sU [a * 64];
        const float* wrow = &swt[a * 32];

        float Uf[8][2];
        #pragma unroll
        for (int kt = 0; kt < 8; ++kt) {
            Uf[kt][0] = Urow[kt * 8 + lr];
            Uf[kt][1] = Urow[kt * 8 + lr + 4];
        }
        float wm[2][2];
        #pragma unroll
        for (int mt = 0; mt < 2; ++mt) {
            wm[mt][0] = wrow[mt * 16 + lq];
            wm[mt][1] = wrow[mt * 16 + lq + 8];
        }

        float D[2][4][4];
        #pragma unroll
        for (int mt = 0; mt < 2; ++mt)
            #pragma unroll
            for (int nt = 0; nt < 4; ++nt)
                #pragma unroll
                for (int q = 0; q < 4; ++q) D[mt][nt][q] = 0.f;

        #pragma unroll
        for (int kt = 0; kt < 8; ++kt) {
            const int f1 = kt * 8 + lr;
            unsigned Ah[2][4], Al[2][4];
            #pragma unroll
            for (int mt = 0; mt < 2; ++mt) {
                const int i1 = mt * 16 + lq;
                float v00 = sV[i1 * 68 + f1];
                float v10 = sV[(i1 + 8) * 68 + f1];
                float v01 = sV[i1 * 68 + f1 + 4];
                float v11 = sV[(i1 + 8) * 68 + f1 + 4];
                float h0 = fmaf(wm[mt][0], v00, Uf[kt][0]);
                float h1 = fmaf(wm[mt][1], v10, Uf[kt][0]);
                float h2 = fmaf(wm[mt][0], v01, Uf[kt][1]);
                float h3 = fmaf(wm[mt][1], v11, Uf[kt][1]);
                h0 = fmaxf(h0, 0.f) + 0.01f * fminf(h0, 0.f);
                h1 = fmaxf(h1, 0.f) + 0.01f * fminf(h1, 0.f);
                h2 = fmaxf(h2, 0.f) + 0.01f * fminf(h2, 0.f);
                h3 = fmaxf(h3, 0.f) + 0.01f * fminf(h3, 0.f);
                Ah[mt][0] = tf32_of(h0);
                Ah[mt][1] = tf32_of(h1);
                Ah[mt][2] = tf32_of(h2);
                Ah[mt][3] = tf32_of(h3);
                Al[mt][0] = tf32_of(h0 - __uint_as_float(Ah[mt][0]));
                Al[mt][1] = tf32_of(h1 - __uint_as_float(Ah[mt][1]));
                Al[mt][2] = tf32_of(h2 - __uint_as_float(Ah[mt][2]));
                Al[mt][3] = tf32_of(h3 - __uint_as_float(Ah[mt][3]));
            }
            #pragma unroll
            for (int nt = 0; nt < 4; ++nt) {
                const int bo = f1 * 36 + nt * 8 + lq;
                unsigned b0h = sW2h[bo], b1h = sW2h[bo + 4 * 36];
                unsigned b0l = sW2l[bo], b1l = sW2l[bo + 4 * 36];
                #pragma unroll
                for (int mt = 0; mt < 2; ++mt) {
                    mma_tf32(D[mt][nt], Ah[mt], b0h, b1h);
                    mma_tf32(D[mt][nt], Ah[mt], b0l, b1l);
                    mma_tf32(D[mt][nt], Al[mt], b0h, b1h);
                }
            }
        }

        const size_t base = (((size_t)b * 32) + a) * 1024;
        #pragma unroll
        for (int mt = 0; mt < 2; ++mt) {
            #pragma unroll
            for (int nt = 0; nt < 4; ++nt) {
                const int i1 = mt * 16 + lq;
                const int n  = nt * 8 + 2 * lr;
                *reinterpret_cast<float2*>(&out[base + i1 * 32 + n]) =
                    make_float2(D[mt][nt][0], D[mt][nt][1]);
                *reinterpret_cast<float2*>(&out[base + (i1 + 8) * 32 + n]) =
                    make_float2(D[mt][nt][2], D[mt][nt][3]);
            }
        }
    }
}

// ---------------------------------------------------------------------------
extern "C" void kernel_launch(void* const* d_in, const int* in_sizes, int n_in,
                              void* d_out, int out_size) {
    const float* states         = (const float*)d_in[0];
    const float* policies       = (const float*)d_in[1];
    const float* actions        = (const float*)d_in[2];
    const float* states_people  = (const float*)d_in[3];
    const float* actions_people = (const float*)d_in[4];
    const float* Wk  = (const float*)d_in[5];
    const float* Wq  = (const float*)d_in[6];
    const float* Wv  = (const float*)d_in[7];
    const float* Wkp = (const float*)d_in[8];
    const float* Wqp = (const float*)d_in[9];
    const float* Wvp = (const float*)d_in[10];
    const float* Wf1 = (const float*)d_in[11];
    const float* Wf2 = (const float*)d_in[12];
    float* out = (float*)d_out;

    k0_all<<<264, 256>>>(Wq, Wk, Wqp, Wkp, Wf2);

    cudaFuncSetAttribute(k1_batch, cudaFuncAttributeMaxDynamicSharedMemorySize, SM1_BYTES);
    k1_batch<<<256, 256, SM1_BYTES>>>(states, policies, actions,
                                      states_people, actions_people,
                                      Wv, Wvp, Wf1, out);

    k2_value<<<256, 256>>>(out);
}

// round 12
// speedup vs baseline: 1.2687x; 1.2687x over previous
#include <cuda_runtime.h>
#include <math.h>

#define BB   256

// out layout: value [B,32,32,32] | weight [B,32,32] | wp [B,32,32]
#define WOFF      (8388608ull)
#define WPOFF     (8650752ull)

typedef unsigned long long ull;

__device__ float g_M [128 * 128];
__device__ float g_Mp[128 * 128];
__device__ float g_U [BB * 32 * 64];
__device__ float g_V [BB * 32 * 64];
__device__ unsigned g_W2h[64 * 32];
__device__ unsigned g_W2l[64 * 32];

// ---- packed f32x2 helpers ----
__device__ __forceinline__ ull pk2(float v) {
    ull r; asm("mov.b64 %0, {%1, %1};" : "=l"(r) : "f"(v)); return r;
}
__device__ __forceinline__ ull ffma2(ull a, ull b, ull c) {
    ull d; asm("fma.rn.f32x2 %0, %1, %2, %3;" : "=l"(d) : "l"(a), "l"(b), "l"(c)); return d;
}
__device__ __forceinline__ float2 upk2(ull v) {
    float2 f; asm("mov.b64 {%0, %1}, %2;" : "=f"(f.x), "=f"(f.y) : "l"(v)); return f;
}

// ---- tf32 helpers ----
__device__ __forceinline__ unsigned tf32_of(float x) {
    unsigned r; asm("cvt.rna.tf32.f32 %0, %1;" : "=r"(r) : "f"(x)); return r;
}
__device__ __forceinline__ void mma_tf32(float d[4], const unsigned a[4],
                                         unsigned b0, unsigned b1) {
    asm("mma.sync.aligned.m16n8k8.row.col.f32.tf32.tf32.f32 "
        "{%0,%1,%2,%3}, {%4,%5,%6,%7}, {%8,%9}, {%0,%1,%2,%3};"
        : "+f"(d[0]), "+f"(d[1]), "+f"(d[2]), "+f"(d[3])
        : "r"(a[0]), "r"(a[1]), "r"(a[2]), "r"(a[3]), "r"(b0), "r"(b1));
}

__device__ __forceinline__ float warp_max(float v) {
    #pragma unroll
    for (int o = 16; o; o >>= 1) v = fmaxf(v, __shfl_xor_sync(0xffffffffu, v, o));
    return v;
}
__device__ __forceinline__ float warp_sum(float v) {
    #pragma unroll
    for (int o = 16; o; o >>= 1) v += __shfl_xor_sync(0xffffffffu, v, o);
    return v;
}

// ---------------------------------------------------------------------------
// Kernel 0 (round-9 measured 9.0us): M/Mp GEMMs + W2 hi/lo split.
// ---------------------------------------------------------------------------
__global__ void k0_all(const float* __restrict__ Wq, const float* __restrict__ Wk,
                       const float* __restrict__ Wqp, const float* __restrict__ Wkp,
                       const float* __restrict__ Wf2) {
    const int bx = blockIdx.x;
    const int t  = threadIdx.x;
    if (bx >= 256) {
        int idx = (bx - 256) * 256 + t;
        float v = Wf2[idx];
        unsigned h = tf32_of(v);
        g_W2h[idx] = h;
        g_W2l[idx] = tf32_of(v - __uint_as_float(h));
        return;
    }
    __shared__ float sA[8 * 128];
    __shared__ float sB[16 * 129];
    __shared__ float sR[128 * 2];
    const int mat = bx >> 7;
    const int e0  = ((bx >> 3) & 15) * 8;
    const int c0  = (bx & 7) * 16;
    const float* A  = mat ? Wqp : Wq;
    const float* Bm = mat ? Wkp : Wk;
    float* out      = mat ? g_Mp : g_M;
    for (int i = t; i < 1024; i += 256) sA[i] = A[e0 * 128 + i];
    for (int i = t; i < 2048; i += 256) {
        int r = i >> 7, d = i & 127;
        sB[r * 129 + d] = Bm[(c0 + r) * 128 + d];
    }
    __syncthreads();
    const int kh = t >> 7, r = (t >> 4) & 7, c = t & 15;
    float acc = 0.f;
    const int d0 = kh * 64;
    #pragma unroll 8
    for (int d = 0; d < 64; ++d)
        acc = fmaf(sA[r * 128 + d0 + d], sB[c * 129 + d0 + d], acc);
    sR[(r * 16 + c) * 2 + kh] = acc;
    __syncthreads();
    if (t < 128) {
        int rr = t >> 4, cc = t & 15;
        out[(e0 + rr) * 128 + c0 + cc] = sR[t * 2] + sR[t * 2 + 1];
    }
}

// ---------------------------------------------------------------------------
// k1 staged fp32 GEMM cores (round-7 proven, untouched).
// ---------------------------------------------------------------------------
__device__ __forceinline__ void mm_chunk128(const float* __restrict__ X, int xstr, int e0,
                                            const float* __restrict__ Ws,
                                            ull acc[4][2], int r0, int l) {
    #pragma unroll 4
    for (int e = 0; e < 32; ++e) {
        ulonglong2 wv = *reinterpret_cast<const ulonglong2*>(&Ws[e * 128 + 4 * l]);
        #pragma unroll
        for (int r = 0; r < 4; ++r) {
            ull xx = pk2(X[(r0 + r) * xstr + e0 + e]);
            acc[r][0] = ffma2(xx, wv.x, acc[r][0]);
            acc[r][1] = ffma2(xx, wv.y, acc[r][1]);
        }
    }
}

__device__ __forceinline__ void mm_chunk64(const float* __restrict__ X, int e0,
                                           const float* __restrict__ Ws,
                                           ull acc[4], int r0, int l) {
    #pragma unroll 4
    for (int e = 0; e < 64; ++e) {
        ull wv = *reinterpret_cast<const ull*>(&Ws[e * 64 + 2 * l]);
        #pragma unroll
        for (int r = 0; r < 4; ++r)
            acc[r] = ffma2(pk2(X[(r0 + r) * 128 + e0 + e]), wv, acc[r]);
    }
}

__device__ __forceinline__ void store128(float* __restrict__ Y, ull acc[4][2],
                                         int r0, int l, bool do_tanh) {
    #pragma unroll
    for (int r = 0; r < 4; ++r) {
        float2 p0 = upk2(acc[r][0]);
        float2 p1 = upk2(acc[r][1]);
        float4 v = make_float4(p0.x, p0.y, p1.x, p1.y);
        if (do_tanh) { v.x = tanhf(v.x); v.y = tanhf(v.y); v.z = tanhf(v.z); v.w = tanhf(v.w); }
        *reinterpret_cast<float4*>(&Y[(r0 + r) * 128 + 4 * l]) = v;
    }
}

// ---------------------------------------------------------------------------
// Kernel 1 (round-7 exact): one block per batch. smem 90,496 B -> 2 blocks/SM.
// ---------------------------------------------------------------------------
#define SM1_BYTES 90496
#define SOFTMAX_SCALE 0.08838834764831843f   // 1/sqrt(128)

#define STAGE(SRC) do {                                                    \
    __syncthreads();                                                       \
    { const float4* s4 = reinterpret_cast<const float4*>(SRC);            \
      float4* d4 = reinterpret_cast<float4*>(s_Wst);                      \
      for (int i = t; i < 1024; i += 256) d4[i] = s4[i]; }                \
    __syncthreads();                                                       \
} while (0)

extern "C" __global__ void __launch_bounds__(256, 2)
k1_batch(const float* __restrict__ states, const float* __restrict__ policies,
         const float* __restrict__ actions, const float* __restrict__ states_people,
         const float* __restrict__ actions_people,
         const float* __restrict__ Wv, const float* __restrict__ Wvp,
         const float* __restrict__ Wf1, float* __restrict__ out) {
    extern __shared__ __align__(16) float sm[];
    float* s_oa  = sm;                 // 32 x 129
    float* s_oap = s_oa  + 4128;       // 32 x 129
    float* s_t   = s_oap + 4128;       // 32 x 128
    float* s_w   = s_t   + 4096;       // 32 x 32
    float* s_wp  = s_w   + 1024;       // 32 x 33
    float* s_A1  = s_wp  + 1056;       // 32 x 64  (early: sc 32x33)
    float* s_C1  = s_A1  + 2048;       // 32 x 64  (early: sp 32x33)
    float* s_Wst = s_C1  + 2048;       // 4096 floats: weight chunk buffer
    float* s_sc  = s_A1;
    float* s_sp  = s_C1;

    const int b = blockIdx.x;
    const int t = threadIdx.x;
    const int w = t >> 5, l = t & 31, r0 = 4 * w;

    const float* ac = actions  + (size_t)b * 1024;
    const float* po = policies + (size_t)b * 1024;

    float d_r[4];
    #pragma unroll
    for (int r = 0; r < 4; ++r)
        d_r[r] = po[(r0 + r) * 32 + l] - ac[(r0 + r) * 32 + l];

    {
        const float* st  = states         + (size_t)b * 32 * 96;
        const float* stp = states_people  + (size_t)b * 32 * 96;
        const float* acp = actions_people + (size_t)b * 1024;
        for (int idx = t; idx < 4096; idx += 256) {
            int i = idx >> 7, c = idx & 127;
            s_oa [i * 129 + c] = (c < 96) ? st [i * 96 + c] : ac [i * 32 + c - 96];
            s_oap[i * 129 + c] = (c < 96) ? stp[i * 96 + c] : acp[i * 32 + c - 96];
        }
    }

    // --- t = oa @ M (staged); scores -> sc ---
    {
        ull a1[4][2] = {{0,0},{0,0},{0,0},{0,0}};
        #pragma unroll 1
        for (int ck = 0; ck < 4; ++ck) {
            STAGE(g_M + ck * 4096);
            mm_chunk128(s_oa, 129, ck * 32, s_Wst, a1, r0, l);
        }
        store128(s_t, a1, r0, l, false);
        float a0 = 0, s1 = 0, s2 = 0, s3 = 0;
        #pragma unroll 4
        for (int f = 0; f < 128; ++f) {
            float oj = s_oa[l * 129 + f];
            a0 = fmaf(s_t[(r0 + 0) * 128 + f], oj, a0);
            s1 = fmaf(s_t[(r0 + 1) * 128 + f], oj, s1);
            s2 = fmaf(s_t[(r0 + 2) * 128 + f], oj, s2);
            s3 = fmaf(s_t[(r0 + 3) * 128 + f], oj, s3);
        }
        s_sc[(r0 + 0) * 33 + l] = a0;  s_sc[(r0 + 1) * 33 + l] = s1;
        s_sc[(r0 + 2) * 33 + l] = s2;  s_sc[(r0 + 3) * 33 + l] = s3;
    }

    // --- tp = oa @ Mp (staged); scores_p -> sp ---
    {
        ull a2[4][2] = {{0,0},{0,0},{0,0},{0,0}};
        #pragma unroll 1
        for (int ck = 0; ck < 4; ++ck) {
            STAGE(g_Mp + ck * 4096);
            mm_chunk128(s_oa, 129, ck * 32, s_Wst, a2, r0, l);
        }
        store128(s_t, a2, r0, l, false);
        float c0 = 0, c1 = 0, c2 = 0, c3 = 0;
        #pragma unroll 4
        for (int f = 0; f < 128; ++f) {
            float pj = s_oap[l * 129 + f];
            c0 = fmaf(s_t[(r0 + 0) * 128 + f], pj, c0);
            c1 = fmaf(s_t[(r0 + 1) * 128 + f], pj, c1);
            c2 = fmaf(s_t[(r0 + 2) * 128 + f], pj, c2);
            c3 = fmaf(s_t[(r0 + 3) * 128 + f], pj, c3);
        }
        s_sp[(r0 + 0) * 33 + l] = c0;  s_sp[(r0 + 1) * 33 + l] = c1;
        s_sp[(r0 + 2) * 33 + l] = c2;  s_sp[(r0 + 3) * 33 + l] = c3;
    }
    __syncthreads();

    // --- column softmaxes ---
    {
        #pragma unroll
        for (int k = 0; k < 4; ++k) {
            int a = w + 8 * k;
            float v  = s_sc[l * 33 + a] * SOFTMAX_SCALE;
            float m  = warp_max(v);
            float e  = expf(v - m);
            float s  = warp_sum(e);
            float wg = e / s;
            s_w[a * 32 + l] = wg;
            out[WOFF + ((size_t)b * 32 + a) * 32 + l] = wg;
            float v2 = s_sp[l * 33 + a] * SOFTMAX_SCALE;
            float m2 = warp_max(v2);
            float e2 = expf(v2 - m2);
            float s2 = warp_sum(e2);
            s_wp[l * 33 + a] = e2 / s2;
        }
    }
    __syncthreads();

    // === va -> A1 ; vp -> V(gmem) ; avp -> C1 ===
    ull a1regs[4];
    {
        ull av[4][2] = {{0,0},{0,0},{0,0},{0,0}};
        #pragma unroll 1
        for (int ck = 0; ck < 4; ++ck) {
            STAGE(Wv + ck * 4096);
            mm_chunk128(s_oa, 129, ck * 32, s_Wst, av, r0, l);
        }
        ull va_pre[4][2];
        #pragma unroll
        for (int r = 0; r < 4; ++r) { va_pre[r][0] = av[r][0]; va_pre[r][1] = av[r][1]; }
        store128(s_t, av, r0, l, true);

        {
            ull acc[4] = {0, 0, 0, 0};
            #pragma unroll 1
            for (int ck = 0; ck < 2; ++ck) {
                STAGE(Wf1 + ck * 4096);
                mm_chunk64(s_t, ck * 64, s_Wst, acc, r0, l);
            }
            #pragma unroll
            for (int r = 0; r < 4; ++r) {
                a1regs[r] = acc[r];
                *reinterpret_cast<float2*>(&s_A1[(r0 + r) * 64 + 2 * l]) = upk2(acc[r]);
            }
        }

        {
            STAGE(Wv + 96 * 128);
            #pragma unroll 4
            for (int e = 0; e < 32; ++e) {
                ulonglong2 wv = *reinterpret_cast<const ulonglong2*>(&s_Wst[e * 128 + 4 * l]);
                #pragma unroll
                for (int r = 0; r < 4; ++r) {
                    ull xx = pk2(__shfl_sync(0xffffffffu, d_r[r], e));
                    va_pre[r][0] = ffma2(xx, wv.x, va_pre[r][0]);
                    va_pre[r][1] = ffma2(xx, wv.y, va_pre[r][1]);
                }
            }
            store128(s_t, va_pre, r0, l, true);
        }

        {
            ull acc[4] = {0, 0, 0, 0};
            #pragma unroll 1
            for (int ck = 0; ck < 2; ++ck) {
                STAGE(Wf1 + ck * 4096);
                mm_chunk64(s_t, ck * 64, s_Wst, acc, r0, l);
            }
            float* gV = g_V + (size_t)b * 2048;
            #pragma unroll
            for (int r = 0; r < 4; ++r) {
                float2 p = upk2(acc[r]);
                float2 a = upk2(a1regs[r]);
                *reinterpret_cast<float2*>(&gV[(r0 + r) * 64 + 2 * l]) =
                    make_float2((p.x - a.x) * 0.03125f, (p.y - a.y) * 0.03125f);
            }
        }

        {
            ull ap[4][2] = {{0,0},{0,0},{0,0},{0,0}};
            #pragma unroll 1
            for (int ck = 0; ck < 4; ++ck) {
                STAGE(Wvp + ck * 4096);
                mm_chunk128(s_oap, 129, ck * 32, s_Wst, ap, r0, l);
            }
            store128(s_t, ap, r0, l, true);
            ull acc[4] = {0, 0, 0, 0};
            #pragma unroll 1
            for (int ck = 0; ck < 2; ++ck) {
                STAGE(Wf1 + 8192 + ck * 4096);
                mm_chunk64(s_t, ck * 64, s_Wst, acc, r0, l);
            }
            #pragma unroll
            for (int r = 0; r < 4; ++r)
                *reinterpret_cast<float2*>(&s_C1[(r0 + r) * 64 + 2 * l]) = upk2(acc[r]);
        }
    }
    __syncthreads();

    for (int idx = t; idx < 1024; idx += 256)
        out[WPOFF + (size_t)b * 1024 + idx] = s_wp[(idx >> 5) * 33 + (idx & 31)];

    {
        const ull* A1u = reinterpret_cast<const ull*>(s_A1);
        const ull* C1u = reinterpret_cast<const ull*>(s_C1);
        ull uacc[4] = {0, 0, 0, 0};
        #pragma unroll 4
        for (int j = 0; j < 32; ++j) {
            ull wv = A1u[j * 32 + l];
            #pragma unroll
            for (int r = 0; r < 4; ++r)
                uacc[r] = ffma2(pk2(s_w[(r0 + r) * 32 + j]), wv, uacc[r]);
        }
        #pragma unroll 4
        for (int p = 0; p < 32; ++p) {
            ull wv = C1u[p * 32 + l];
            #pragma unroll
            for (int r = 0; r < 4; ++r)
                uacc[r] = ffma2(pk2(s_wp[(r0 + r) * 33 + p]), wv, uacc[r]);
        }
        float* gU = g_U + (size_t)b * 2048;
        #pragma unroll
        for (int r = 0; r < 4; ++r) {
            float2 p = upk2(uacc[r]);
            *reinterpret_cast<float2*>(&gU[(r0 + r) * 64 + 2 * l]) =
                make_float2(p.x * 0.03125f, p.y * 0.03125f);
        }
    }
}

// ---------------------------------------------------------------------------
// Kernel 2 (round-7 structure, 1024 blocks, warp=agent):
// W2 pre-split + register diet (U loaded in-loop) + 4 blocks/SM.
// ---------------------------------------------------------------------------
extern "C" __global__ void __launch_bounds__(256, 4)
k2_value(float* __restrict__ out) {
    __shared__ float    sV [32 * 68];
    __shared__ float    sU [8 * 64];
    __shared__ float    swt[8 * 33];
    __shared__ unsigned sW2h[64 * 36];
    __shared__ unsigned sW2l[64 * 36];

    const int t  = threadIdx.x;
    const int b  = blockIdx.x >> 2;
    const int a0 = (blockIdx.x & 3) * 8;

    for (int idx = t; idx < 2048; idx += 256) {
        int i = idx >> 6, f = idx & 63;
        sV[i * 68 + f] = g_V[(size_t)b * 2048 + idx];
    }
    for (int idx = t; idx < 512; idx += 256)
        sU[idx] = g_U[(size_t)b * 2048 + a0 * 64 + idx];
    {
        int a = t >> 5, i = t & 31;
        swt[a * 33 + i] = out[WOFF + ((size_t)b * 32 + a0 + a) * 32 + i];
    }
    for (int idx = t; idx < 2048; idx += 256) {
        int f = idx >> 5, n = idx & 31;
        sW2h[f * 36 + n] = g_W2h[idx];
        sW2l[f * 36 + n] = g_W2l[idx];
    }
    __syncthreads();

    const int w = t >> 5, l = t & 31;
    const int lq = l >> 2;
    const int lr = l & 3;
    const float* Urow = &sU [w * 64];
    const float* wrow = &swt[w * 33];

    float wm[2][2];
    #pragma unroll
    for (int mt = 0; mt < 2; ++mt) {
        wm[mt][0] = wrow[mt * 16 + lq];
        wm[mt][1] = wrow[mt * 16 + lq + 8];
    }

    float D[2][4][4];
    #pragma unroll
    for (int mt = 0; mt < 2; ++mt)
        #pragma unroll
        for (int nt = 0; nt < 4; ++nt)
            #pragma unroll
            for (int q = 0; q < 4; ++q) D[mt][nt][q] = 0.f;

    #pragma unroll
    for (int kt = 0; kt < 8; ++kt) {
        const int f1 = kt * 8 + lr;
        const float U0 = Urow[kt * 8 + lr];          // in-loop LDS (register diet)
        const float U1 = Urow[kt * 8 + lr + 4];
        unsigned Ah[2][4], Al[2][4];
        #pragma unroll
        for (int mt = 0; mt < 2; ++mt) {
            const int i1 = mt * 16 + lq;
            float v00 = sV[i1 * 68 + f1];
            float v10 = sV[(i1 + 8) * 68 + f1];
            float v01 = sV[i1 * 68 + f1 + 4];
            float v11 = sV[(i1 + 8) * 68 + f1 + 4];
            float h0 = fmaf(wm[mt][0], v00, U0);
            float h1 = fmaf(wm[mt][1], v10, U0);
            float h2 = fmaf(wm[mt][0], v01, U1);
            float h3 = fmaf(wm[mt][1], v11, U1);
            h0 = fmaxf(h0, 0.f) + 0.01f * fminf(h0, 0.f);
            h1 = fmaxf(h1, 0.f) + 0.01f * fminf(h1, 0.f);
            h2 = fmaxf(h2, 0.f) + 0.01f * fminf(h2, 0.f);
            h3 = fmaxf(h3, 0.f) + 0.01f * fminf(h3, 0.f);
            Ah[mt][0] = tf32_of(h0);
            Ah[mt][1] = tf32_of(h1);
            Ah[mt][2] = tf32_of(h2);
            Ah[mt][3] = tf32_of(h3);
            Al[mt][0] = tf32_of(h0 - __uint_as_float(Ah[mt][0]));
            Al[mt][1] = tf32_of(h1 - __uint_as_float(Ah[mt][1]));
            Al[mt][2] = tf32_of(h2 - __uint_as_float(Ah[mt][2]));
            Al[mt][3] = tf32_of(h3 - __uint_as_float(Ah[mt][3]));
        }
        #pragma unroll
        for (int nt = 0; nt < 4; ++nt) {
            const int bo = f1 * 36 + nt * 8 + lq;
            unsigned b0h = sW2h[bo], b1h = sW2h[bo + 4 * 36];
            unsigned b0l = sW2l[bo], b1l = sW2l[bo + 4 * 36];
            #pragma unroll
            for (int mt = 0; mt < 2; ++mt) {
                mma_tf32(D[mt][nt], Ah[mt], b0h, b1h);
                mma_tf32(D[mt][nt], Ah[mt], b0l, b1l);
                mma_tf32(D[mt][nt], Al[mt], b0h, b1h);
            }
        }
    }

    const size_t base = (((size_t)b * 32) + a0 + w) * 1024;
    #pragma unroll
    for (int mt = 0; mt < 2; ++mt) {
        #pragma unroll
        for (int nt = 0; nt < 4; ++nt) {
            const int i1 = mt * 16 + lq;
            const int n  = nt * 8 + 2 * lr;
            *reinterpret_cast<float2*>(&out[base + i1 * 32 + n]) =
                make_float2(D[mt][nt][0], D[mt][nt][1]);
            *reinterpret_cast<float2*>(&out[base + (i1 + 8) * 32 + n]) =
                make_float2(D[mt][nt][2], D[mt][nt][3]);
        }
    }
}

// ---------------------------------------------------------------------------
extern "C" void kernel_launch(void* const* d_in, const int* in_sizes, int n_in,
                              void* d_out, int out_size) {
    const float* states         = (const float*)d_in[0];
    const float* policies       = (const float*)d_in[1];
    const float* actions        = (const float*)d_in[2];
    const float* states_people  = (const float*)d_in[3];
    const float* actions_people = (const float*)d_in[4];
    const float* Wk  = (const float*)d_in[5];
    const float* Wq  = (const float*)d_in[6];
    const float* Wv  = (const float*)d_in[7];
    const float* Wkp = (const float*)d_in[8];
    const float* Wqp = (const float*)d_in[9];
    const float* Wvp = (const float*)d_in[10];
    const float* Wf1 = (const float*)d_in[11];
    const float* Wf2 = (const float*)d_in[12];
    float* out = (float*)d_out;

    k0_all<<<264, 256>>>(Wq, Wk, Wqp, Wkp, Wf2);

    cudaFuncSetAttribute(k1_batch, cudaFuncAttributeMaxDynamicSharedMemorySize, SM1_BYTES);
    k1_batch<<<256, 256, SM1_BYTES>>>(states, policies, actions,
                                      states_people, actions_people,
                                      Wv, Wvp, Wf1, out);

    k2_value<<<1024, 256>>>(out);
}